// round 8
// baseline (speedup 1.0000x reference)
#include <cuda_runtime.h>
#include <cuda_bf16.h>
#include <math.h>

// ---------------------------------------------------------------------------
//   x:        (64, 32, 128, 128) f32
//   grid:     (1, 4096, 1, 2)    f32   values in [-0.1, 0.1]
//   features: (1, 160, 1, 4096)  f32
//   bias:     (4096,)            f32
//   out:      (64, 4096)         f32
// ---------------------------------------------------------------------------

#define NB   64
#define NC   32
#define HW   128
#define OUTD 4096

// 5x5 Gaussian (exact reference values) — used for the up-sample (hi) taps
__constant__ float c_G[25] = {
    0.003765f, 0.015019f, 0.023792f, 0.015019f, 0.003765f,
    0.015019f, 0.059912f, 0.094907f, 0.059912f, 0.015019f,
    0.023792f, 0.094907f, 0.150342f, 0.094907f, 0.023792f,
    0.015019f, 0.059912f, 0.094907f, 0.059912f, 0.015019f,
    0.003765f, 0.015019f, 0.023792f, 0.015019f, 0.003765f};

// separable factor: g x g == G to <= 4e-7 per tap
__constant__ float c_g[5] = {0.06136f, 0.24477f, 0.38774f, 0.24477f, 0.06136f};

// Per-level window metadata. level sizes: 128, 64, 32, 16, 8
__constant__ int cIMGW[5] = {128, 64, 32, 16, 8};
__constant__ int cW0[5]   = {56, 27, 12, 5, 2};
__constant__ int cWW[5]   = {16, 10, 8, 6, 4};
__constant__ int cWOFF[5] = {0, 256, 356, 420, 456};
// total window pixels = 256+100+64+36+16 = 472

// Scratch: win[pix][c][n], n fastest. 472*32*64 floats = 3.87 MB (L2-resident)
__device__ float g_win[472 * NC * NB];

// up(lo)(y,x): transposed-conv upsample tap sum (zero-padded), no 4x factor.
__device__ __forceinline__ float up5(const float* lo, int L, int y, int x) {
    float acc = 0.f;
#pragma unroll
    for (int ky = 0; ky < 5; ky++) {
        int yy = y + ky - 2;
        if (yy & 1) continue;
        yy >>= 1;
        if ((unsigned)yy >= (unsigned)L) continue;
        const float* row = lo + yy * L;
#pragma unroll
        for (int kx = 0; kx < 5; kx++) {
            int xx = x + kx - 2;
            if (xx & 1) continue;
            xx >>= 1;
            if ((unsigned)xx >= (unsigned)L) continue;
            acc = fmaf(c_G[ky * 5 + kx], row[xx], acc);
        }
    }
    return acc;
}

// Separable smem->smem downsample, 4-wide vectorized. S=64/32/16.
template <int S>
__device__ __forceinline__ void sep_down(const float* __restrict__ src,
                                         float* __restrict__ tmp,
                                         float* __restrict__ dst, int tid) {
    constexpr int D = S / 2;
    constexpr int JC = D / 4;               // 4-wide col chunks
    // pass1 (horizontal): tmp[r][j0..j0+3]
    for (int task = tid; task < S * JC; task += 256) {
        int ch = task & (JC - 1);
        int r  = task / JC;
        int j0 = 4 * ch;
        const float* row = src + r * S;
        float v[11];
#pragma unroll
        for (int k = 0; k < 11; k++) {
            int cc = 2 * j0 - 2 + k;
            v[k] = ((unsigned)cc < (unsigned)S) ? row[cc] : 0.f;
        }
        float4 o;
        o.x = c_g[0]*v[0] + c_g[1]*v[1] + c_g[2]*v[2] + c_g[3]*v[3] + c_g[4]*v[4];
        o.y = c_g[0]*v[2] + c_g[1]*v[3] + c_g[2]*v[4] + c_g[3]*v[5] + c_g[4]*v[6];
        o.z = c_g[0]*v[4] + c_g[1]*v[5] + c_g[2]*v[6] + c_g[3]*v[7] + c_g[4]*v[8];
        o.w = c_g[0]*v[6] + c_g[1]*v[7] + c_g[2]*v[8] + c_g[3]*v[9] + c_g[4]*v[10];
        *(float4*)(tmp + r * D + j0) = o;
    }
    __syncthreads();
    // pass2 (vertical): 2 rows x 4 cols per task
    for (int task = tid; task < (D / 2) * JC; task += 256) {
        int ch = task & (JC - 1);
        int ic = task / JC;
        int i0 = 2 * ic, j0 = 4 * ch;
        float4 rv[7];
#pragma unroll
        for (int k = 0; k < 7; k++) {
            int rr = 2 * i0 - 2 + k;
            rv[k] = ((unsigned)rr < (unsigned)S)
                  ? *(const float4*)(tmp + rr * D + j0)
                  : make_float4(0.f, 0.f, 0.f, 0.f);
        }
        float4 a = make_float4(0.f, 0.f, 0.f, 0.f);
        float4 b = make_float4(0.f, 0.f, 0.f, 0.f);
#pragma unroll
        for (int m = 0; m < 5; m++) {
            float g = c_g[m];
            a.x = fmaf(g, rv[m].x, a.x);     a.y = fmaf(g, rv[m].y, a.y);
            a.z = fmaf(g, rv[m].z, a.z);     a.w = fmaf(g, rv[m].w, a.w);
            b.x = fmaf(g, rv[m + 2].x, b.x); b.y = fmaf(g, rv[m + 2].y, b.y);
            b.z = fmaf(g, rv[m + 2].z, b.z); b.w = fmaf(g, rv[m + 2].w, b.w);
        }
        *(float4*)(dst + i0 * D + j0) = a;
        *(float4*)(dst + (i0 + 1) * D + j0) = b;
    }
    __syncthreads();
}

// ---------------------------------------------------------------------------
// Phase A: one block per (n, c) slice. Separable pyramid in SMEM, vectorized.
// ---------------------------------------------------------------------------
__global__ __launch_bounds__(256) void phaseA(const float* __restrict__ xin) {
    extern __shared__ float s_tmp[];        // 128*64 floats = 32 KB (dynamic)
    __shared__ float lo0[64 * 64];
    __shared__ float lo1[32 * 32];
    __shared__ float lo2[16 * 16];
    __shared__ float lo3[8 * 8];

    const int blk = blockIdx.x;             // n*32 + c
    const int tid = threadIdx.x;
    const float* __restrict__ base = xin + (size_t)blk * (HW * HW);

    // ---- level0 pass1 (horizontal, global -> s_tmp[128][64]) ----
    // 1024 tasks: one row r, 8 outputs (j0 = 8*tj).
    // Source cols needed: 16tj-4 .. 16tj+16 -> 6 aligned float4 loads (v[24]),
    // zero-filled outside [0,127] (matches reference zero padding).
#pragma unroll
    for (int it = 0; it < 4; it++) {
        int task = tid + it * 256;
        int tj = task & 7;
        int r  = task >> 3;
        const float* row = base + r * 128;
        float v[24];
#pragma unroll
        for (int q = 0; q < 6; q++) {
            int cb = 16 * tj - 4 + 4 * q;
            if (cb >= 0 && cb <= 124) {
                float4 t = *(const float4*)(row + cb);
                v[4*q] = t.x; v[4*q+1] = t.y; v[4*q+2] = t.z; v[4*q+3] = t.w;
            } else {
                v[4*q] = v[4*q+1] = v[4*q+2] = v[4*q+3] = 0.f;
            }
        }
        float o[8];
#pragma unroll
        for (int jl = 0; jl < 8; jl++) {
            float acc = 0.f;
#pragma unroll
            for (int m = 0; m < 5; m++)
                acc = fmaf(c_g[m], v[2 * jl + 2 + m], acc);
            o[jl] = acc;
        }
        *(float4*)(s_tmp + r * 64 + 8 * tj)     = make_float4(o[0], o[1], o[2], o[3]);
        *(float4*)(s_tmp + r * 64 + 8 * tj + 4) = make_float4(o[4], o[5], o[6], o[7]);
    }
    __syncthreads();

    // ---- level0 pass2 (vertical, s_tmp[128][64] -> lo0[64][64]) ----
    // 512 tasks: 2 rows x 4 cols each, float4 LDS.
#pragma unroll
    for (int it = 0; it < 2; it++) {
        int task = tid + it * 256;
        int jc = task & 15;
        int ic = task >> 4;
        int i0 = 2 * ic, j0 = 4 * jc;
        float4 rv[7];
#pragma unroll
        for (int k = 0; k < 7; k++) {
            int rr = 2 * i0 - 2 + k;
            rv[k] = ((unsigned)rr < 128u)
                  ? *(const float4*)(s_tmp + rr * 64 + j0)
                  : make_float4(0.f, 0.f, 0.f, 0.f);
        }
        float4 a = make_float4(0.f, 0.f, 0.f, 0.f);
        float4 b = make_float4(0.f, 0.f, 0.f, 0.f);
#pragma unroll
        for (int m = 0; m < 5; m++) {
            float g = c_g[m];
            a.x = fmaf(g, rv[m].x, a.x);     a.y = fmaf(g, rv[m].y, a.y);
            a.z = fmaf(g, rv[m].z, a.z);     a.w = fmaf(g, rv[m].w, a.w);
            b.x = fmaf(g, rv[m + 2].x, b.x); b.y = fmaf(g, rv[m + 2].y, b.y);
            b.z = fmaf(g, rv[m + 2].z, b.z); b.w = fmaf(g, rv[m + 2].w, b.w);
        }
        *(float4*)(lo0 + i0 * 64 + j0) = a;
        *(float4*)(lo0 + (i0 + 1) * 64 + j0) = b;
    }
    __syncthreads();

    sep_down<64>(lo0, s_tmp, lo1, tid);
    sep_down<32>(lo1, s_tmp, lo2, tid);
    sep_down<16>(lo2, s_tmp, lo3, tid);

    const int c = blk & 31;
    const int n = blk >> 5;
    const int cn = c * NB + n;

    // level 0 window: 16x16 at [56,71] on 128x128 (x re-read via L2)
    {
        int p = tid;
        int y = 56 + (p >> 4), x = 56 + (p & 15);
        float v = __ldg(base + y * 128 + x) - 4.f * up5(lo0, 64, y, x);
        g_win[(size_t)p * (NC * NB) + cn] = v;
    }
    // levels 1..4: 100 + 64 + 36 + 16 = 216 pixels
    if (tid < 216) {
        int p = tid;
        float v;
        int off;
        if (p < 100) {                      // hi1: 10x10 at [27,36] on 64x64
            int y = 27 + p / 10, x = 27 + p % 10;
            v = lo0[y * 64 + x] - 4.f * up5(lo1, 32, y, x);
            off = 256 + p;
        } else if (p < 164) {               // hi2: 8x8 at [12,19] on 32x32
            int q = p - 100;
            int y = 12 + (q >> 3), x = 12 + (q & 7);
            v = lo1[y * 32 + x] - 4.f * up5(lo2, 16, y, x);
            off = 356 + q;
        } else if (p < 200) {               // hi3: 6x6 at [5,10] on 16x16
            int q = p - 164;
            int y = 5 + q / 6, x = 5 + q % 6;
            v = lo2[y * 16 + x] - 4.f * up5(lo3, 8, y, x);
            off = 420 + q;
        } else {                            // lo3 residual: 4x4 at [2,5] on 8x8
            int q = p - 200;
            int y = 2 + (q >> 2), x = 2 + (q & 3);
            v = lo3[y * 8 + x];
            off = 456 + q;
        }
        g_win[(size_t)off * (NC * NB) + cn] = v;
    }
}

// ---------------------------------------------------------------------------
// Phase B: exact R2 version (measured 36.2us — best of 5 variants tried).
// 1024 blocks x 256 threads. Block = 4 outputs (o) x 64 batch (n), scalar.
// ---------------------------------------------------------------------------
__global__ __launch_bounds__(256) void phaseB(const float* __restrict__ grid,
                                              const float* __restrict__ features,
                                              const float* __restrict__ bias,
                                              float* __restrict__ out) {
    __shared__ __align__(16) float fsm[160 * 4];   // [lc][oo]

    const int o0 = blockIdx.x << 2;
    const int tid = threadIdx.x;

    if (tid < 160)
        ((float4*)fsm)[tid] = *(const float4*)(features + (size_t)tid * OUTD + o0);
    __syncthreads();

    const int n  = tid & 63;
    const int oo = tid >> 6;
    const int o  = o0 + oo;

    float gx = fminf(fmaxf(grid[2 * o], -1.f), 1.f);
    float gy = fminf(fmaxf(grid[2 * o + 1], -1.f), 1.f);

    float acc = 0.f;

#pragma unroll
    for (int l = 0; l < 5; l++) {
        const float Wl = (float)cIMGW[l];
        float fx = ((gx + 1.f) * Wl - 1.f) * 0.5f;
        float fy = ((gy + 1.f) * Wl - 1.f) * 0.5f;
        float x0f = floorf(fx), y0f = floorf(fy);
        float wx = fx - x0f, wy = fy - y0f;

        const int ww = cWW[l];
        int px = (int)x0f - cW0[l];
        int py = (int)y0f - cW0[l];
        px = max(0, min(px, ww - 2));       // safety clamp (never hit in practice)
        py = max(0, min(py, ww - 2));

        const float* b00 = g_win + ((size_t)(cWOFF[l] + py * ww + px)) * (NC * NB) + n;
        const float* b01 = b00 + (NC * NB);
        const float* b10 = b00 + (size_t)ww * (NC * NB);
        const float* b11 = b10 + (NC * NB);

        const float w00 = (1.f - wx) * (1.f - wy);
        const float w01 = wx * (1.f - wy);
        const float w10 = (1.f - wx) * wy;
        const float w11 = wx * wy;

#pragma unroll 8
        for (int c = 0; c < 32; c++) {
            float f   = fsm[(l * 32 + c) * 4 + oo];
            float v00 = b00[c * NB];
            float v01 = b01[c * NB];
            float v10 = b10[c * NB];
            float v11 = b11[c * NB];
            acc = fmaf(f, fmaf(w00, v00, fmaf(w01, v01, fmaf(w10, v10, w11 * v11))), acc);
        }
    }

    out[(size_t)n * OUTD + o] = acc + bias[o];
}

// ---------------------------------------------------------------------------
extern "C" void kernel_launch(void* const* d_in, const int* in_sizes, int n_in,
                              void* d_out, int out_size) {
    (void)in_sizes; (void)n_in; (void)out_size;
    const float* x        = (const float*)d_in[0];
    const float* grid     = (const float*)d_in[1];
    const float* features = (const float*)d_in[2];
    const float* bias     = (const float*)d_in[3];
    float* out            = (float*)d_out;

    // Opt-in: 21.25 KB static + 32 KB dynamic > 48 KB default limit.
    cudaFuncSetAttribute(phaseA, cudaFuncAttributeMaxDynamicSharedMemorySize,
                         128 * 64 * sizeof(float));

    phaseA<<<NB * NC, 256, 128 * 64 * sizeof(float)>>>(x);
    phaseB<<<OUTD / 4, 256>>>(grid, features, bias, out);
}

// round 9
// speedup vs baseline: 1.1799x; 1.1799x over previous
#include <cuda_runtime.h>
#include <cuda_bf16.h>
#include <math.h>

// ---------------------------------------------------------------------------
//   x:        (64, 32, 128, 128) f32
//   grid:     (1, 4096, 1, 2)    f32   values in [-0.1, 0.1]
//   features: (1, 160, 1, 4096)  f32
//   bias:     (4096,)            f32
//   out:      (64, 4096)         f32
// ---------------------------------------------------------------------------

#define NB   64
#define NC   32
#define HW   128
#define OUTD 4096

// 5x5 Gaussian (exact reference values) — used for the up-sample (hi) taps
__constant__ float c_G[25] = {
    0.003765f, 0.015019f, 0.023792f, 0.015019f, 0.003765f,
    0.015019f, 0.059912f, 0.094907f, 0.059912f, 0.015019f,
    0.023792f, 0.094907f, 0.150342f, 0.094907f, 0.023792f,
    0.015019f, 0.059912f, 0.094907f, 0.059912f, 0.015019f,
    0.003765f, 0.015019f, 0.023792f, 0.015019f, 0.003765f};

// separable factor: g x g == G to <= 4e-7 per tap
__constant__ float c_g[5] = {0.06136f, 0.24477f, 0.38774f, 0.24477f, 0.06136f};

// Per-level window metadata. level sizes: 128, 64, 32, 16, 8
__constant__ int cIMGW[5] = {128, 64, 32, 16, 8};
__constant__ int cW0[5]   = {56, 27, 12, 5, 2};
__constant__ int cWW[5]   = {16, 10, 8, 6, 4};
__constant__ int cWOFF[5] = {0, 256, 356, 420, 456};
// total window pixels = 256+100+64+36+16 = 472

// Scratch: win[pix][c][n], n fastest. 472*32*64 floats = 3.87 MB (L2-resident)
__device__ float g_win[472 * NC * NB];

// up(lo)(y,x): transposed-conv upsample tap sum (zero-padded), no 4x factor.
__device__ __forceinline__ float up5(const float* lo, int L, int y, int x) {
    float acc = 0.f;
#pragma unroll
    for (int ky = 0; ky < 5; ky++) {
        int yy = y + ky - 2;
        if (yy & 1) continue;
        yy >>= 1;
        if ((unsigned)yy >= (unsigned)L) continue;
        const float* row = lo + yy * L;
#pragma unroll
        for (int kx = 0; kx < 5; kx++) {
            int xx = x + kx - 2;
            if (xx & 1) continue;
            xx >>= 1;
            if ((unsigned)xx >= (unsigned)L) continue;
            acc = fmaf(c_G[ky * 5 + kx], row[xx], acc);
        }
    }
    return acc;
}

// Separable smem->smem downsample for small levels (S=64,32,16).
// (exact R4 version — measured as part of phaseA=41us)
template <int S>
__device__ __forceinline__ void sep_down(const float* __restrict__ src,
                                         float* __restrict__ tmp,
                                         float* __restrict__ dst, int tid) {
    constexpr int D = S / 2;
    for (int idx = tid; idx < S * D; idx += 256) {
        int r = idx / D, j = idx - r * D;
        const float* row = src + r * S;
        float acc = 0.f;
#pragma unroll
        for (int k = 0; k < 5; k++) {
            int xc = 2 * j + k - 2;
            if ((unsigned)xc < (unsigned)S) acc = fmaf(c_g[k], row[xc], acc);
        }
        tmp[idx] = acc;
    }
    __syncthreads();
    for (int idx = tid; idx < D * D; idx += 256) {
        int i = idx / D, j = idx - i * D;
        float acc = 0.f;
#pragma unroll
        for (int k = 0; k < 5; k++) {
            int yy = 2 * i + k - 2;
            if ((unsigned)yy < (unsigned)S) acc = fmaf(c_g[k], tmp[yy * D + j], acc);
        }
        dst[idx] = acc;
    }
    __syncthreads();
}

// ---------------------------------------------------------------------------
// Phase A: EXACT R4 version (measured 41us). One block per (n, c) slice.
// ---------------------------------------------------------------------------
__global__ __launch_bounds__(256) void phaseA(const float* __restrict__ xin) {
    extern __shared__ float s_tmp[];        // 128*64 floats = 32 KB (dynamic)
    __shared__ float lo0[64 * 64];
    __shared__ float lo1[32 * 32];
    __shared__ float lo2[16 * 16];
    __shared__ float lo3[8 * 8];

    const int blk = blockIdx.x;             // n*32 + c
    const int tid = threadIdx.x;
    const float* __restrict__ base = xin + (size_t)blk * (HW * HW);

    // ---- level0 pass1 (horizontal, global -> s_tmp[128][64]) ----
#pragma unroll
    for (int it = 0; it < 8; it++) {
        int task = tid + it * 256;          // 2048 tasks
        int tj = task & 15;                 // j0 = 4*tj
        int r  = task >> 4;
        const float* row = base + r * 128;
        int cb0 = 8 * tj - 4;
        float v[16];
#pragma unroll
        for (int q = 0; q < 4; q++) {
            int cb = cb0 + 4 * q;
            if (cb >= 0 && cb <= 124) {
                float4 t = *(const float4*)(row + cb);
                v[4 * q] = t.x; v[4 * q + 1] = t.y; v[4 * q + 2] = t.z; v[4 * q + 3] = t.w;
            } else {
                v[4 * q] = v[4 * q + 1] = v[4 * q + 2] = v[4 * q + 3] = 0.f;
            }
        }
#pragma unroll
        for (int jl = 0; jl < 4; jl++) {
            float acc = 0.f;
#pragma unroll
            for (int k = 0; k < 5; k++)
                acc = fmaf(c_g[k], v[2 * jl + k + 2], acc);
            s_tmp[r * 64 + 4 * tj + jl] = acc;
        }
    }
    __syncthreads();

    // ---- level0 pass2 (vertical, s_tmp -> lo0[64][64]) ----
#pragma unroll
    for (int it = 0; it < 4; it++) {
        int task = tid + it * 256;          // 1024 tasks
        int j  = task & 63;
        int i0 = (task >> 6) * 4;
        float vr[11];
#pragma unroll
        for (int s = 0; s < 11; s++) {
            int rr = 2 * i0 - 2 + s;
            vr[s] = ((unsigned)rr < 128u) ? s_tmp[rr * 64 + j] : 0.f;
        }
#pragma unroll
        for (int di = 0; di < 4; di++) {
            float acc = 0.f;
#pragma unroll
            for (int k = 0; k < 5; k++)
                acc = fmaf(c_g[k], vr[2 * di + k], acc);
            lo0[(i0 + di) * 64 + j] = acc;
        }
    }
    __syncthreads();

    sep_down<64>(lo0, s_tmp, lo1, tid);
    sep_down<32>(lo1, s_tmp, lo2, tid);
    sep_down<16>(lo2, s_tmp, lo3, tid);

    const int c = blk & 31;
    const int n = blk >> 5;
    const int cn = c * NB + n;

    // level 0 window: 16x16 at [56,71] on 128x128 (x re-read via L2)
    {
        int p = tid;
        int y = 56 + (p >> 4), x = 56 + (p & 15);
        float v = __ldg(base + y * 128 + x) - 4.f * up5(lo0, 64, y, x);
        g_win[(size_t)p * (NC * NB) + cn] = v;
    }
    // levels 1..4: 100 + 64 + 36 + 16 = 216 pixels
    if (tid < 216) {
        int p = tid;
        float v;
        int off;
        if (p < 100) {                      // hi1: 10x10 at [27,36] on 64x64
            int y = 27 + p / 10, x = 27 + p % 10;
            v = lo0[y * 64 + x] - 4.f * up5(lo1, 32, y, x);
            off = 256 + p;
        } else if (p < 164) {               // hi2: 8x8 at [12,19] on 32x32
            int q = p - 100;
            int y = 12 + (q >> 3), x = 12 + (q & 7);
            v = lo1[y * 32 + x] - 4.f * up5(lo2, 16, y, x);
            off = 356 + q;
        } else if (p < 200) {               // hi3: 6x6 at [5,10] on 16x16
            int q = p - 164;
            int y = 5 + q / 6, x = 5 + q % 6;
            v = lo2[y * 16 + x] - 4.f * up5(lo3, 8, y, x);
            off = 420 + q;
        } else {                            // lo3 residual: 4x4 at [2,5] on 8x8
            int q = p - 200;
            int y = 2 + (q >> 2), x = 2 + (q & 3);
            v = lo3[y * 8 + x];
            off = 456 + q;
        }
        g_win[(size_t)off * (NC * NB) + cn] = v;
    }
}

// ---------------------------------------------------------------------------
// Phase B: EXACT R2 version (measured 36.2-36.4us — best of 6 variants).
// 1024 blocks x 256 threads. Block = 4 outputs (o) x 64 batch (n), scalar.
// ---------------------------------------------------------------------------
__global__ __launch_bounds__(256) void phaseB(const float* __restrict__ grid,
                                              const float* __restrict__ features,
                                              const float* __restrict__ bias,
                                              float* __restrict__ out) {
    __shared__ __align__(16) float fsm[160 * 4];   // [lc][oo]

    const int o0 = blockIdx.x << 2;
    const int tid = threadIdx.x;

    if (tid < 160)
        ((float4*)fsm)[tid] = *(const float4*)(features + (size_t)tid * OUTD + o0);
    __syncthreads();

    const int n  = tid & 63;
    const int oo = tid >> 6;
    const int o  = o0 + oo;

    float gx = fminf(fmaxf(grid[2 * o], -1.f), 1.f);
    float gy = fminf(fmaxf(grid[2 * o + 1], -1.f), 1.f);

    float acc = 0.f;

#pragma unroll
    for (int l = 0; l < 5; l++) {
        const float Wl = (float)cIMGW[l];
        float fx = ((gx + 1.f) * Wl - 1.f) * 0.5f;
        float fy = ((gy + 1.f) * Wl - 1.f) * 0.5f;
        float x0f = floorf(fx), y0f = floorf(fy);
        float wx = fx - x0f, wy = fy - y0f;

        const int ww = cWW[l];
        int px = (int)x0f - cW0[l];
        int py = (int)y0f - cW0[l];
        px = max(0, min(px, ww - 2));       // safety clamp (never hit in practice)
        py = max(0, min(py, ww - 2));

        const float* b00 = g_win + ((size_t)(cWOFF[l] + py * ww + px)) * (NC * NB) + n;
        const float* b01 = b00 + (NC * NB);
        const float* b10 = b00 + (size_t)ww * (NC * NB);
        const float* b11 = b10 + (NC * NB);

        const float w00 = (1.f - wx) * (1.f - wy);
        const float w01 = wx * (1.f - wy);
        const float w10 = (1.f - wx) * wy;
        const float w11 = wx * wy;

#pragma unroll 8
        for (int c = 0; c < 32; c++) {
            float f   = fsm[(l * 32 + c) * 4 + oo];
            float v00 = b00[c * NB];
            float v01 = b01[c * NB];
            float v10 = b10[c * NB];
            float v11 = b11[c * NB];
            acc = fmaf(f, fmaf(w00, v00, fmaf(w01, v01, fmaf(w10, v10, w11 * v11))), acc);
        }
    }

    out[(size_t)n * OUTD + o] = acc + bias[o];
}

// ---------------------------------------------------------------------------
extern "C" void kernel_launch(void* const* d_in, const int* in_sizes, int n_in,
                              void* d_out, int out_size) {
    (void)in_sizes; (void)n_in; (void)out_size;
    const float* x        = (const float*)d_in[0];
    const float* grid     = (const float*)d_in[1];
    const float* features = (const float*)d_in[2];
    const float* bias     = (const float*)d_in[3];
    float* out            = (float*)d_out;

    // Opt-in: 21.25 KB static + 32 KB dynamic > 48 KB default limit.
    cudaFuncSetAttribute(phaseA, cudaFuncAttributeMaxDynamicSharedMemorySize,
                         128 * 64 * sizeof(float));

    phaseA<<<NB * NC, 256, 128 * 64 * sizeof(float)>>>(x);
    phaseB<<<OUTD / 4, 256>>>(grid, features, bias, out);
}

// round 10
// speedup vs baseline: 1.1991x; 1.0163x over previous
#include <cuda_runtime.h>
#include <cuda_bf16.h>
#include <math.h>

// ---------------------------------------------------------------------------
//   x:        (64, 32, 128, 128) f32
//   grid:     (1, 4096, 1, 2)    f32   values in [-0.1, 0.1]
//   features: (1, 160, 1, 4096)  f32
//   bias:     (4096,)            f32
//   out:      (64, 4096)         f32
// ---------------------------------------------------------------------------

#define NB   64
#define NC   32
#define HW   128
#define OUTD 4096

// 5x5 Gaussian (exact reference values) — used for the up-sample (hi) taps
__constant__ float c_G[25] = {
    0.003765f, 0.015019f, 0.023792f, 0.015019f, 0.003765f,
    0.015019f, 0.059912f, 0.094907f, 0.059912f, 0.015019f,
    0.023792f, 0.094907f, 0.150342f, 0.094907f, 0.023792f,
    0.015019f, 0.059912f, 0.094907f, 0.059912f, 0.015019f,
    0.003765f, 0.015019f, 0.023792f, 0.015019f, 0.003765f};

// separable factor: g x g == G to <= 4e-7 per tap
__constant__ float c_g[5] = {0.06136f, 0.24477f, 0.38774f, 0.24477f, 0.06136f};

// Per-level window metadata. level sizes: 128, 64, 32, 16, 8
__constant__ int cIMGW[5] = {128, 64, 32, 16, 8};
__constant__ int cW0[5]   = {56, 27, 12, 5, 2};
__constant__ int cWW[5]   = {16, 10, 8, 6, 4};
__constant__ int cWOFF[5] = {0, 256, 356, 420, 456};
// total window pixels = 256+100+64+36+16 = 472

// Scratch: win[pix][c][n], n fastest. 472*32*64 floats = 3.87 MB (L2-resident)
__device__ float g_win[472 * NC * NB];

// up(lo)(y,x): transposed-conv upsample tap sum (zero-padded), no 4x factor.
__device__ __forceinline__ float up5(const float* lo, int L, int y, int x) {
    float acc = 0.f;
#pragma unroll
    for (int ky = 0; ky < 5; ky++) {
        int yy = y + ky - 2;
        if (yy & 1) continue;
        yy >>= 1;
        if ((unsigned)yy >= (unsigned)L) continue;
        const float* row = lo + yy * L;
#pragma unroll
        for (int kx = 0; kx < 5; kx++) {
            int xx = x + kx - 2;
            if (xx & 1) continue;
            xx >>= 1;
            if ((unsigned)xx >= (unsigned)L) continue;
            acc = fmaf(c_G[ky * 5 + kx], row[xx], acc);
        }
    }
    return acc;
}

// Separable smem->smem downsample for small levels (S=64,32,16).
// (exact R4 version — measured as part of phaseA)
template <int S>
__device__ __forceinline__ void sep_down(const float* __restrict__ src,
                                         float* __restrict__ tmp,
                                         float* __restrict__ dst, int tid) {
    constexpr int D = S / 2;
    for (int idx = tid; idx < S * D; idx += 256) {
        int r = idx / D, j = idx - r * D;
        const float* row = src + r * S;
        float acc = 0.f;
#pragma unroll
        for (int k = 0; k < 5; k++) {
            int xc = 2 * j + k - 2;
            if ((unsigned)xc < (unsigned)S) acc = fmaf(c_g[k], row[xc], acc);
        }
        tmp[idx] = acc;
    }
    __syncthreads();
    for (int idx = tid; idx < D * D; idx += 256) {
        int i = idx / D, j = idx - i * D;
        float acc = 0.f;
#pragma unroll
        for (int k = 0; k < 5; k++) {
            int yy = 2 * i + k - 2;
            if ((unsigned)yy < (unsigned)S) acc = fmaf(c_g[k], tmp[yy * D + j], acc);
        }
        dst[idx] = acc;
    }
    __syncthreads();
}

// ---------------------------------------------------------------------------
// Phase A: R9 structure + (1) depth-1 prefetch in level0 pass1 to double
// DRAM MLP, (2) hi0 x-window pre-staged to SMEM (kills the latency-exposed
// __ldg tail).
// ---------------------------------------------------------------------------
__global__ __launch_bounds__(256) void phaseA(const float* __restrict__ xin) {
    extern __shared__ float s_tmp[];        // 128*64 floats = 32 KB (dynamic)
    __shared__ float lo0[64 * 64];
    __shared__ float lo1[32 * 32];
    __shared__ float lo2[16 * 16];
    __shared__ float lo3[8 * 8];
    __shared__ float xwin[16 * 16];         // x[56..71][56..71]

    const int blk = blockIdx.x;             // n*32 + c
    const int tid = threadIdx.x;
    const float* __restrict__ base = xin + (size_t)blk * (HW * HW);

    // ---- pre-stage hi0 x-window (overlaps with pass1 DRAM stream) ----
    if (tid < 64) {
        int rr = tid >> 2, qq = tid & 3;    // cols 56+4qq are 16B-aligned
        *(float4*)(xwin + rr * 16 + 4 * qq) =
            *(const float4*)(base + (56 + rr) * 128 + 56 + 4 * qq);
    }
    // (visibility guaranteed by the barriers below, used only in final stage)

    // ---- level0 pass1 (horizontal, global -> s_tmp[128][64]) ----
    // task = tid + 256*it: column tj = tid&15 fixed, row = r0 + 16*it.
    // Depth-1 prefetch: issue it+1's loads before it's FMAs/stores.
    {
        const int tj  = tid & 15;            // j0 = 4*tj
        const int r0  = tid >> 4;            // row r = r0 + 16*it
        const int cb0 = 8 * tj - 4;
        bool gq[4];
#pragma unroll
        for (int q = 0; q < 4; q++) {
            int cb = cb0 + 4 * q;
            gq[q] = (cb >= 0 && cb <= 124);
        }
        float4 pf[4];
#pragma unroll
        for (int q = 0; q < 4; q++)
            pf[q] = gq[q] ? *(const float4*)(base + r0 * 128 + cb0 + 4 * q)
                          : make_float4(0.f, 0.f, 0.f, 0.f);
#pragma unroll
        for (int it = 0; it < 8; it++) {
            float v[16];
            v[0]=pf[0].x; v[1]=pf[0].y; v[2]=pf[0].z; v[3]=pf[0].w;
            v[4]=pf[1].x; v[5]=pf[1].y; v[6]=pf[1].z; v[7]=pf[1].w;
            v[8]=pf[2].x; v[9]=pf[2].y; v[10]=pf[2].z; v[11]=pf[2].w;
            v[12]=pf[3].x; v[13]=pf[3].y; v[14]=pf[3].z; v[15]=pf[3].w;
            if (it < 7) {
                const float* rowp = base + (r0 + 16 * (it + 1)) * 128;
#pragma unroll
                for (int q = 0; q < 4; q++)
                    pf[q] = gq[q] ? *(const float4*)(rowp + cb0 + 4 * q)
                                  : make_float4(0.f, 0.f, 0.f, 0.f);
            }
            const int r = r0 + 16 * it;
#pragma unroll
            for (int jl = 0; jl < 4; jl++) {
                float acc = 0.f;
#pragma unroll
                for (int k = 0; k < 5; k++)
                    acc = fmaf(c_g[k], v[2 * jl + k + 2], acc);
                s_tmp[r * 64 + 4 * tj + jl] = acc;
            }
        }
    }
    __syncthreads();

    // ---- level0 pass2 (vertical, s_tmp -> lo0[64][64]) ----
#pragma unroll
    for (int it = 0; it < 4; it++) {
        int task = tid + it * 256;          // 1024 tasks
        int j  = task & 63;
        int i0 = (task >> 6) * 4;
        float vr[11];
#pragma unroll
        for (int s = 0; s < 11; s++) {
            int rr = 2 * i0 - 2 + s;
            vr[s] = ((unsigned)rr < 128u) ? s_tmp[rr * 64 + j] : 0.f;
        }
#pragma unroll
        for (int di = 0; di < 4; di++) {
            float acc = 0.f;
#pragma unroll
            for (int k = 0; k < 5; k++)
                acc = fmaf(c_g[k], vr[2 * di + k], acc);
            lo0[(i0 + di) * 64 + j] = acc;
        }
    }
    __syncthreads();

    sep_down<64>(lo0, s_tmp, lo1, tid);
    sep_down<32>(lo1, s_tmp, lo2, tid);
    sep_down<16>(lo2, s_tmp, lo3, tid);

    const int c = blk & 31;
    const int n = blk >> 5;
    const int cn = c * NB + n;

    // level 0 window: 16x16 at [56,71] on 128x128 (x from pre-staged SMEM)
    {
        int p = tid;
        int y = 56 + (p >> 4), x = 56 + (p & 15);
        float v = xwin[p] - 4.f * up5(lo0, 64, y, x);
        g_win[(size_t)p * (NC * NB) + cn] = v;
    }
    // levels 1..4: 100 + 64 + 36 + 16 = 216 pixels
    if (tid < 216) {
        int p = tid;
        float v;
        int off;
        if (p < 100) {                      // hi1: 10x10 at [27,36] on 64x64
            int y = 27 + p / 10, x = 27 + p % 10;
            v = lo0[y * 64 + x] - 4.f * up5(lo1, 32, y, x);
            off = 256 + p;
        } else if (p < 164) {               // hi2: 8x8 at [12,19] on 32x32
            int q = p - 100;
            int y = 12 + (q >> 3), x = 12 + (q & 7);
            v = lo1[y * 32 + x] - 4.f * up5(lo2, 16, y, x);
            off = 356 + q;
        } else if (p < 200) {               // hi3: 6x6 at [5,10] on 16x16
            int q = p - 164;
            int y = 5 + q / 6, x = 5 + q % 6;
            v = lo2[y * 16 + x] - 4.f * up5(lo3, 8, y, x);
            off = 420 + q;
        } else {                            // lo3 residual: 4x4 at [2,5] on 8x8
            int q = p - 200;
            int y = 2 + (q >> 2), x = 2 + (q & 3);
            v = lo3[y * 8 + x];
            off = 456 + q;
        }
        g_win[(size_t)off * (NC * NB) + cn] = v;
    }
}

// ---------------------------------------------------------------------------
// Phase B: EXACT R2 version (measured 36.2-37.3us — best of 6 variants).
// 1024 blocks x 256 threads. Block = 4 outputs (o) x 64 batch (n), scalar.
// ---------------------------------------------------------------------------
__global__ __launch_bounds__(256) void phaseB(const float* __restrict__ grid,
                                              const float* __restrict__ features,
                                              const float* __restrict__ bias,
                                              float* __restrict__ out) {
    __shared__ __align__(16) float fsm[160 * 4];   // [lc][oo]

    const int o0 = blockIdx.x << 2;
    const int tid = threadIdx.x;

    if (tid < 160)
        ((float4*)fsm)[tid] = *(const float4*)(features + (size_t)tid * OUTD + o0);
    __syncthreads();

    const int n  = tid & 63;
    const int oo = tid >> 6;
    const int o  = o0 + oo;

    float gx = fminf(fmaxf(grid[2 * o], -1.f), 1.f);
    float gy = fminf(fmaxf(grid[2 * o + 1], -1.f), 1.f);

    float acc = 0.f;

#pragma unroll
    for (int l = 0; l < 5; l++) {
        const float Wl = (float)cIMGW[l];
        float fx = ((gx + 1.f) * Wl - 1.f) * 0.5f;
        float fy = ((gy + 1.f) * Wl - 1.f) * 0.5f;
        float x0f = floorf(fx), y0f = floorf(fy);
        float wx = fx - x0f, wy = fy - y0f;

        const int ww = cWW[l];
        int px = (int)x0f - cW0[l];
        int py = (int)y0f - cW0[l];
        px = max(0, min(px, ww - 2));       // safety clamp (never hit in practice)
        py = max(0, min(py, ww - 2));

        const float* b00 = g_win + ((size_t)(cWOFF[l] + py * ww + px)) * (NC * NB) + n;
        const float* b01 = b00 + (NC * NB);
        const float* b10 = b00 + (size_t)ww * (NC * NB);
        const float* b11 = b10 + (NC * NB);

        const float w00 = (1.f - wx) * (1.f - wy);
        const float w01 = wx * (1.f - wy);
        const float w10 = (1.f - wx) * wy;
        const float w11 = wx * wy;

#pragma unroll 8
        for (int c = 0; c < 32; c++) {
            float f   = fsm[(l * 32 + c) * 4 + oo];
            float v00 = b00[c * NB];
            float v01 = b01[c * NB];
            float v10 = b10[c * NB];
            float v11 = b11[c * NB];
            acc = fmaf(f, fmaf(w00, v00, fmaf(w01, v01, fmaf(w10, v10, w11 * v11))), acc);
        }
    }

    out[(size_t)n * OUTD + o] = acc + bias[o];
}

// ---------------------------------------------------------------------------
extern "C" void kernel_launch(void* const* d_in, const int* in_sizes, int n_in,
                              void* d_out, int out_size) {
    (void)in_sizes; (void)n_in; (void)out_size;
    const float* x        = (const float*)d_in[0];
    const float* grid     = (const float*)d_in[1];
    const float* features = (const float*)d_in[2];
    const float* bias     = (const float*)d_in[3];
    float* out            = (float*)d_out;

    // Opt-in: 22.25 KB static + 32 KB dynamic > 48 KB default limit.
    cudaFuncSetAttribute(phaseA, cudaFuncAttributeMaxDynamicSharedMemorySize,
                         128 * 64 * sizeof(float));

    phaseA<<<NB * NC, 256, 128 * 64 * sizeof(float)>>>(x);
    phaseB<<<OUTD / 4, 256>>>(grid, features, bias, out);
}